// round 14
// baseline (speedup 1.0000x reference)
#include <cuda_runtime.h>
#include <cuda_fp16.h>
#include <cstdint>

// GCN layer on GB300, round-14: R13 + (1) aggregate/gemm 2-way chunked
// cross-stream overlap, (2) quad-grouped fp16 adder tree in aggregate.
//   A: init -> degree -> scan -> fill -> agg(h0) -> agg(h1) -> gemm(h1)
//   D: gemm(h0) (overlaps agg(h1))
//   B: nhs (after scan, overlaps fill)   C: eh copy (fully parallel)

#define NN 100000
#define EE 1600000
#define DD 128
#define MTILES 6250        // 100000/16
#define NHALF 50000        // nodes per chunk
#define MTHALF 3125        // mtiles per chunk
#define NBLK 391           // ceil(NN/256)
#define WSTRIDE 136
#define SMEM_GEMM (2 * DD * WSTRIDE * (int)sizeof(__half))   // 69,632B

__device__ __align__(128) int     g_cnt[NN];
__device__ __align__(128) int     g_off[NN];
__device__ __align__(128) int     g_cur[NN];
__device__ __align__(128) unsigned long long g_comb[NBLK];  // scan state
__device__ __align__(128) int     g_esrc[EE];
__device__ __align__(128) float   g_dis[NN];
__device__ __align__(128) __half2 g_nhs[(size_t)NN * 64];  // nh*dis fp16
__device__ __align__(128) __half2 g_xh [(size_t)NN * 64];  // agg fp16
__device__ unsigned g_odd_or;   // 0 => edge_index is int64 (zero high words)

// ---------- helpers ----------
__device__ __forceinline__ int edge_idx(const void* ei, int table, int e, bool is64) {
    if (is64) return (int)((const long long*)ei)[(size_t)table * EE + e];
    return ((const int*)ei)[(size_t)table * EE + e];
}
__device__ __forceinline__ uint32_t h2bits(__half2 h) {
    return *reinterpret_cast<uint32_t*>(&h);
}
__device__ __forceinline__ uint32_t packh2(float a, float b) {
    __half2 h = __floats2half2_rn(a, b);
    return *reinterpret_cast<uint32_t*>(&h);
}
__device__ __forceinline__ void mma16816(float c[4], const uint32_t a[4],
                                         uint32_t b0, uint32_t b1) {
    asm volatile(
        "mma.sync.aligned.m16n8k16.row.col.f32.f16.f16.f32 "
        "{%0,%1,%2,%3}, {%4,%5,%6,%7}, {%8,%9}, {%0,%1,%2,%3};"
        : "+f"(c[0]), "+f"(c[1]), "+f"(c[2]), "+f"(c[3])
        : "r"(a[0]), "r"(a[1]), "r"(a[2]), "r"(a[3]), "r"(b0), "r"(b1));
}

// ---------- init: zero counters + scan state, block 0 detects idx dtype ----
__global__ void init_kernel(const unsigned* __restrict__ ei_words) {
    int i = blockIdx.x * 256 + threadIdx.x;
    if (i < NN) g_cnt[i] = 0;
    if (i < NBLK) g_comb[i] = 0ull;
    if (blockIdx.x == 0) {
        __shared__ unsigned sred[256];
        unsigned v = 0;
        #pragma unroll
        for (int j = 0; j < 16; ++j)
            v |= ei_words[2 * (threadIdx.x + 256 * j) + 1];
        sred[threadIdx.x] = v;
        __syncthreads();
        #pragma unroll
        for (int o = 128; o > 0; o >>= 1) {
            if (threadIdx.x < o) sred[threadIdx.x] |= sred[threadIdx.x + o];
            __syncthreads();
        }
        if (threadIdx.x == 0) g_odd_or = sred[0];
    }
}

// ---------- degree histogram ----------
__global__ void degree_kernel(const void* __restrict__ ei) {
    int e = blockIdx.x * blockDim.x + threadIdx.x;
    if (e >= EE) return;
    bool is64 = (g_odd_or == 0u);
    unsigned dst = (unsigned)edge_idx(ei, 1, e, is64);
    if (dst < NN) atomicAdd(&g_cnt[dst], 1);
}

// ---------- single-pass scan (decoupled lookback) ----------
__global__ void __launch_bounds__(256) scan_kernel() {
    __shared__ int s[256];
    __shared__ int sprefix;
    const int tid = threadIdx.x, b = blockIdx.x;
    int i = b * 256 + tid;
    int v = (i < NN) ? g_cnt[i] : 0;
    s[tid] = v;
    __syncthreads();
    #pragma unroll
    for (int o = 1; o < 256; o <<= 1) {
        int x = (tid >= o) ? s[tid - o] : 0;
        __syncthreads();
        s[tid] += x;
        __syncthreads();
    }
    int agg = s[255];
    if (tid == 0) {
        if (b == 0) {
            sprefix = 0;
            atomicExch(&g_comb[0], (2ull << 32) | (unsigned)agg);
        } else {
            atomicExch(&g_comb[b], (1ull << 32) | (unsigned)agg);
        }
    }
    if (b > 0 && tid < 32) {
        const int lane = tid;
        int prefix = 0;
        int base = b - 1;
        while (true) {
            int idx = base - lane;
            unsigned long long c;
            unsigned st;
            do {
                c = (idx >= 0) ? atomicAdd(&g_comb[idx], 0ull) : (2ull << 32);
                st = (unsigned)(c >> 32);
            } while (__any_sync(0xffffffffu, st == 0));
            int val = (int)(c & 0xffffffffu);
            unsigned m2 = __ballot_sync(0xffffffffu, st == 2);
            if (m2) {
                int firstp = __ffs(m2) - 1;
                int contrib = (lane <= firstp) ? val : 0;
                prefix += __reduce_add_sync(0xffffffffu, contrib);
                break;
            }
            prefix += __reduce_add_sync(0xffffffffu, val);
            base -= 32;
        }
        if (lane == 0) {
            atomicExch(&g_comb[b], (2ull << 32) | (unsigned)(prefix + agg));
            sprefix = prefix;
        }
    }
    __syncthreads();
    if (i < NN) {
        int excl = sprefix + s[tid] - v;
        g_off[i] = excl;
        g_cur[i] = excl;
        g_dis[i] = (v > 0) ? rsqrtf((float)v) : 0.f;
    }
}

// ---------- bucket fill ----------
__global__ void fill_kernel(const void* __restrict__ ei) {
    int e = blockIdx.x * blockDim.x + threadIdx.x;
    if (e >= EE) return;
    bool is64 = (g_odd_or == 0u);
    int src = edge_idx(ei, 0, e, is64);
    int dst = edge_idx(ei, 1, e, is64);
    if ((unsigned)src >= NN || (unsigned)dst >= NN) return;
    int pos = atomicAdd(&g_cur[dst], 1);
    g_esrc[pos] = src;
}

// ---------- nhs: g_nhs[i] = fp16(nh[i] * dis[row]) (stream B) ----------
__global__ void nhs_kernel(const float* __restrict__ nh) {
    int idx = blockIdx.x * blockDim.x + threadIdx.x;
    if (idx < NN * 32) {
        int row = idx >> 5;
        float d = __ldg(&g_dis[row]);
        float4 v = __ldg(reinterpret_cast<const float4*>(nh) + idx);
        g_nhs[2 * idx]     = __floats2half2_rn(v.x * d, v.y * d);
        g_nhs[2 * idx + 1] = __floats2half2_rn(v.z * d, v.w * d);
    }
}

// ---------- aggregate: warp per node, quad fp16 adder tree ----------
// g_xh[d] = fp16( (sum_e g_nhs[src_e]) * dis[d] ); 4 edges per step summed
// in fp16 (hadd2 tree), one cvt+fp32-accumulate per quad.
__global__ void aggregate_kernel(int nodeBase) {
    int w = nodeBase + ((blockIdx.x * blockDim.x + threadIdx.x) >> 5);
    int lane = threadIdx.x & 31;
    if (w >= NN) return;
    int off = g_off[w], len = g_cnt[w];
    float4 acc = make_float4(0.f, 0.f, 0.f, 0.f);
    const float2* NHS = reinterpret_cast<const float2*>(g_nhs);
    for (int b = 0; b < len; b += 32) {
        int n = min(32, len - b);
        int src = (lane < n) ? __ldg(&g_esrc[off + b + lane]) : 0;
        int i = 0;
        #pragma unroll 2
        for (; i + 4 <= n; i += 4) {
            int s0 = __shfl_sync(0xffffffffu, src, i);
            int s1 = __shfl_sync(0xffffffffu, src, i + 1);
            int s2 = __shfl_sync(0xffffffffu, src, i + 2);
            int s3 = __shfl_sync(0xffffffffu, src, i + 3);
            float2 r0 = __ldg(NHS + (size_t)s0 * 32 + lane);
            float2 r1 = __ldg(NHS + (size_t)s1 * 32 + lane);
            float2 r2 = __ldg(NHS + (size_t)s2 * 32 + lane);
            float2 r3 = __ldg(NHS + (size_t)s3 * 32 + lane);
            __half2 qx = __hadd2(
                __hadd2(*reinterpret_cast<__half2*>(&r0.x),
                        *reinterpret_cast<__half2*>(&r1.x)),
                __hadd2(*reinterpret_cast<__half2*>(&r2.x),
                        *reinterpret_cast<__half2*>(&r3.x)));
            __half2 qy = __hadd2(
                __hadd2(*reinterpret_cast<__half2*>(&r0.y),
                        *reinterpret_cast<__half2*>(&r1.y)),
                __hadd2(*reinterpret_cast<__half2*>(&r2.y),
                        *reinterpret_cast<__half2*>(&r3.y)));
            float2 f0 = __half22float2(qx), f1 = __half22float2(qy);
            acc.x += f0.x; acc.y += f0.y; acc.z += f1.x; acc.w += f1.y;
        }
        for (; i + 2 <= n; i += 2) {
            int s0 = __shfl_sync(0xffffffffu, src, i);
            int s1 = __shfl_sync(0xffffffffu, src, i + 1);
            float2 r0 = __ldg(NHS + (size_t)s0 * 32 + lane);
            float2 r1 = __ldg(NHS + (size_t)s1 * 32 + lane);
            __half2 p0 = __hadd2(*reinterpret_cast<__half2*>(&r0.x),
                                 *reinterpret_cast<__half2*>(&r1.x));
            __half2 p1 = __hadd2(*reinterpret_cast<__half2*>(&r0.y),
                                 *reinterpret_cast<__half2*>(&r1.y));
            float2 f0 = __half22float2(p0), f1 = __half22float2(p1);
            acc.x += f0.x; acc.y += f0.y; acc.z += f1.x; acc.w += f1.y;
        }
        if (i < n) {
            int s0 = __shfl_sync(0xffffffffu, src, i);
            float2 r0 = __ldg(NHS + (size_t)s0 * 32 + lane);
            float2 f0 = __half22float2(*reinterpret_cast<__half2*>(&r0.x));
            float2 f1 = __half22float2(*reinterpret_cast<__half2*>(&r0.y));
            acc.x += f0.x; acc.y += f0.y; acc.z += f1.x; acc.w += f1.y;
        }
    }
    float dd = g_dis[w];
    g_xh[(size_t)w * 64 + lane * 2]     = __floats2half2_rn(acc.x * dd, acc.y * dd);
    g_xh[(size_t)w * 64 + lane * 2 + 1] = __floats2half2_rn(acc.z * dd, acc.w * dd);
}

// ---------- fused GEMM1+GEMM2, register-chained HMMA (tile range) ----------
__global__ void __launch_bounds__(256) gemm12_kernel(
    const float* __restrict__ W1, const float* __restrict__ b1,
    const float* __restrict__ W2, const float* __restrict__ b2,
    float* __restrict__ out, int mtBase, int mtEnd) {
    extern __shared__ __half sW[];
    __half* sW1 = sW;
    __half* sW2 = sW + DD * WSTRIDE;
    const int tid = threadIdx.x, lane = tid & 31, warp = tid >> 5;
    const int gid = lane >> 2, tq = lane & 3;

    for (int idx = tid; idx < DD * DD; idx += 256) {
        int k = idx >> 7, n = idx & 127;
        sW1[n * WSTRIDE + k] = __float2half(W1[idx]);
        sW2[n * WSTRIDE + k] = __float2half(W2[idx]);
    }
    __syncthreads();

    for (int mt = mtBase + blockIdx.x * 8 + warp; mt < mtEnd;
         mt += gridDim.x * 8) {
        const __half2* X0 = g_xh + (size_t)(mt * 16 + gid) * 64;
        const __half2* X1 = X0 + 8 * 64;

        float acc1[16][4];
        #pragma unroll
        for (int t = 0; t < 16; ++t)
            acc1[t][0] = acc1[t][1] = acc1[t][2] = acc1[t][3] = 0.f;
        #pragma unroll
        for (int kc = 0; kc < 8; ++kc) {
            uint32_t a[4];
            a[0] = h2bits(__ldg(X0 + kc * 8 + tq));
            a[1] = h2bits(__ldg(X1 + kc * 8 + tq));
            a[2] = h2bits(__ldg(X0 + kc * 8 + 4 + tq));
            a[3] = h2bits(__ldg(X1 + kc * 8 + 4 + tq));
            #pragma unroll
            for (int t = 0; t < 16; ++t) {
                int n = 8 * t + gid;
                uint32_t b0 = h2bits(*reinterpret_cast<const __half2*>(
                    &sW1[n * WSTRIDE + kc * 16 + 2 * tq]));
                uint32_t b1v = h2bits(*reinterpret_cast<const __half2*>(
                    &sW1[n * WSTRIDE + kc * 16 + 8 + 2 * tq]));
                mma16816(acc1[t], a, b0, b1v);
            }
        }

        float acc2[16][4];
        #pragma unroll
        for (int t = 0; t < 16; ++t)
            acc2[t][0] = acc2[t][1] = acc2[t][2] = acc2[t][3] = 0.f;
        #pragma unroll
        for (int kc = 0; kc < 8; ++kc) {
            int t0 = 2 * kc, t1 = 2 * kc + 1;
            float2 bbA = __ldg(reinterpret_cast<const float2*>(b1 + 8 * t0 + 2 * tq));
            float2 bbB = __ldg(reinterpret_cast<const float2*>(b1 + 8 * t1 + 2 * tq));
            uint32_t ha[4];
            ha[0] = packh2(fmaxf(acc1[t0][0] + bbA.x, 0.f),
                           fmaxf(acc1[t0][1] + bbA.y, 0.f));
            ha[1] = packh2(fmaxf(acc1[t0][2] + bbA.x, 0.f),
                           fmaxf(acc1[t0][3] + bbA.y, 0.f));
            ha[2] = packh2(fmaxf(acc1[t1][0] + bbB.x, 0.f),
                           fmaxf(acc1[t1][1] + bbB.y, 0.f));
            ha[3] = packh2(fmaxf(acc1[t1][2] + bbB.x, 0.f),
                           fmaxf(acc1[t1][3] + bbB.y, 0.f));
            #pragma unroll
            for (int t = 0; t < 16; ++t) {
                int n = 8 * t + gid;
                uint32_t b0 = h2bits(*reinterpret_cast<const __half2*>(
                    &sW2[n * WSTRIDE + kc * 16 + 2 * tq]));
                uint32_t b1v = h2bits(*reinterpret_cast<const __half2*>(
                    &sW2[n * WSTRIDE + kc * 16 + 8 + 2 * tq]));
                mma16816(acc2[t], ha, b0, b1v);
            }
        }

        size_t r0 = (size_t)(mt * 16 + gid) * DD;
        size_t r1 = r0 + (size_t)8 * DD;
        #pragma unroll
        for (int t = 0; t < 16; ++t) {
            int n0 = 8 * t + 2 * tq;
            float2 bb = __ldg(reinterpret_cast<const float2*>(b2 + n0));
            *reinterpret_cast<float2*>(out + r0 + n0) =
                make_float2(acc2[t][0] + bb.x, acc2[t][1] + bb.y);
            *reinterpret_cast<float2*>(out + r1 + n0) =
                make_float2(acc2[t][2] + bb.x, acc2[t][3] + bb.y);
        }
    }
}

// ---------- eh passthrough (stream C) ----------
__global__ void copy_eh_kernel(const float* __restrict__ eh, float* __restrict__ out) {
    int idx = blockIdx.x * blockDim.x + threadIdx.x;
    const int total4 = EE * 16 / 4;
    if (idx < total4)
        reinterpret_cast<float4*>(out)[idx] =
            __ldg(reinterpret_cast<const float4*>(eh) + idx);
}

extern "C" void kernel_launch(void* const* d_in, const int* in_sizes, int n_in,
                              void* d_out, int out_size) {
    const float* nh = nullptr; const float* eh = nullptr; const void* ei = nullptr;
    const float* Wp[2] = {nullptr, nullptr}; const float* bp[2] = {nullptr, nullptr};
    int nw = 0, nb = 0;
    for (int i = 0; i < n_in; ++i) {
        int s = in_sizes[i];
        if (s == NN * DD)            nh = (const float*)d_in[i];
        else if (s == EE * 16)       eh = (const float*)d_in[i];
        else if (s == 2 * EE)        ei = d_in[i];
        else if (s == DD * DD) { if (nw < 2) Wp[nw++] = (const float*)d_in[i]; }
        else if (s == DD)      { if (nb < 2) bp[nb++] = (const float*)d_in[i]; }
    }
    float* out = (float*)d_out;

    // Lazy one-time setup (first call is uncaptured; reused inside capture).
    static cudaStream_t sB = nullptr, sC = nullptr, sD = nullptr;
    static cudaEvent_t evFork = nullptr, evScan = nullptr, evNhs = nullptr,
                       evEh = nullptr, evAgg0 = nullptr, evG0 = nullptr;
    static bool attrSet = false;
    if (!sB) {
        cudaStreamCreateWithFlags(&sB, cudaStreamNonBlocking);
        cudaStreamCreateWithFlags(&sC, cudaStreamNonBlocking);
        cudaStreamCreateWithFlags(&sD, cudaStreamNonBlocking);
        cudaEventCreateWithFlags(&evFork, cudaEventDisableTiming);
        cudaEventCreateWithFlags(&evScan, cudaEventDisableTiming);
        cudaEventCreateWithFlags(&evNhs,  cudaEventDisableTiming);
        cudaEventCreateWithFlags(&evEh,   cudaEventDisableTiming);
        cudaEventCreateWithFlags(&evAgg0, cudaEventDisableTiming);
        cudaEventCreateWithFlags(&evG0,   cudaEventDisableTiming);
    }
    if (!attrSet) {
        cudaFuncSetAttribute(gemm12_kernel,
                             cudaFuncAttributeMaxDynamicSharedMemorySize, SMEM_GEMM);
        attrSet = true;
    }

    // ---- stream C: eh passthrough (fully independent) ----
    cudaEventRecord(evFork, 0);
    cudaStreamWaitEvent(sC, evFork, 0);
    copy_eh_kernel<<<(EE * 16 / 4 + 255) / 256, 256, 0, sC>>>(
        eh, out + (size_t)NN * DD);
    cudaEventRecord(evEh, sC);

    // ---- stream A: CSR chain ----
    init_kernel<<<NBLK, 256>>>((const unsigned*)ei);
    degree_kernel<<<(EE + 255) / 256, 256>>>(ei);
    scan_kernel<<<NBLK, 256>>>();
    cudaEventRecord(evScan, 0);
    fill_kernel<<<(EE + 255) / 256, 256>>>(ei);

    // ---- stream B: pre-scaled fp16 features (overlaps fill) ----
    cudaStreamWaitEvent(sB, evScan, 0);
    nhs_kernel<<<(NN * 32 + 255) / 256, 256, 0, sB>>>(nh);
    cudaEventRecord(evNhs, sB);

    // ---- chunked aggregate || gemm pipeline ----
    cudaStreamWaitEvent(0, evNhs, 0);
    aggregate_kernel<<<NHALF * 32 / 256, 256>>>(0);
    cudaEventRecord(evAgg0, 0);
    // stream D: gemm for half0 overlaps aggregate of half1
    cudaStreamWaitEvent(sD, evAgg0, 0);
    gemm12_kernel<<<296, 256, SMEM_GEMM, sD>>>(
        Wp[0], bp[0], Wp[1], bp[1], out, 0, MTHALF);
    cudaEventRecord(evG0, sD);
    // stream A: aggregate half1, then gemm half1
    aggregate_kernel<<<NHALF * 32 / 256, 256>>>(NHALF);
    gemm12_kernel<<<296, 256, SMEM_GEMM>>>(
        Wp[0], bp[0], Wp[1], bp[1], out, MTHALF, MTILES);

    // join
    cudaStreamWaitEvent(0, evG0, 0);
    cudaStreamWaitEvent(0, evEh, 0);
}

// round 15
// speedup vs baseline: 1.0531x; 1.0531x over previous
#include <cuda_runtime.h>
#include <cuda_fp16.h>
#include <cstdint>

// GCN layer on GB300, round-15: R13 pipeline + block-cooperative GEMM with
// W held as per-warp register A-fragments (ldmatrix), X/H tiles in smem.
//   A: init -> degree -> scan -> fill -> aggregate -> gemm12
//   B: nhs (after scan, overlaps fill)   C: eh copy (fully parallel)

#define NN 100000
#define EE 1600000
#define DD 128
#define MTILES 6250        // 100000/16
#define NBLK 391           // ceil(NN/256)

__device__ __align__(128) int     g_cnt[NN];
__device__ __align__(128) int     g_off[NN];
__device__ __align__(128) int     g_cur[NN];
__device__ __align__(128) unsigned long long g_comb[NBLK];  // scan state
__device__ __align__(128) int     g_esrc[EE];
__device__ __align__(128) float   g_dis[NN];
__device__ __align__(128) __half2 g_nhs[(size_t)NN * 64];  // nh*dis fp16
__device__ __align__(128) __half2 g_xh [(size_t)NN * 64];  // agg fp16
__device__ unsigned g_odd_or;   // 0 => edge_index is int64 (zero high words)

// ---------- helpers ----------
__device__ __forceinline__ int edge_idx(const void* ei, int table, int e, bool is64) {
    if (is64) return (int)((const long long*)ei)[(size_t)table * EE + e];
    return ((const int*)ei)[(size_t)table * EE + e];
}
__device__ __forceinline__ uint32_t sptr(const void* p) {
    return (uint32_t)__cvta_generic_to_shared(p);
}
__device__ __forceinline__ void ldsm4(uint32_t r[4], uint32_t addr) {
    asm volatile("ldmatrix.sync.aligned.m8n8.x4.shared.b16 {%0,%1,%2,%3}, [%4];"
                 : "=r"(r[0]), "=r"(r[1]), "=r"(r[2]), "=r"(r[3]) : "r"(addr));
}
__device__ __forceinline__ void mma16816(float c[4], const uint32_t a[4],
                                         uint32_t b0, uint32_t b1) {
    asm volatile(
        "mma.sync.aligned.m16n8k16.row.col.f32.f16.f16.f32 "
        "{%0,%1,%2,%3}, {%4,%5,%6,%7}, {%8,%9}, {%0,%1,%2,%3};"
        : "+f"(c[0]), "+f"(c[1]), "+f"(c[2]), "+f"(c[3])
        : "r"(a[0]), "r"(a[1]), "r"(a[2]), "r"(a[3]), "r"(b0), "r"(b1));
}

// ---------- init: zero counters + scan state, block 0 detects idx dtype ----
__global__ void init_kernel(const unsigned* __restrict__ ei_words) {
    int i = blockIdx.x * 256 + threadIdx.x;
    if (i < NN) g_cnt[i] = 0;
    if (i < NBLK) g_comb[i] = 0ull;
    if (blockIdx.x == 0) {
        __shared__ unsigned sred[256];
        unsigned v = 0;
        #pragma unroll
        for (int j = 0; j < 16; ++j)
            v |= ei_words[2 * (threadIdx.x + 256 * j) + 1];
        sred[threadIdx.x] = v;
        __syncthreads();
        #pragma unroll
        for (int o = 128; o > 0; o >>= 1) {
            if (threadIdx.x < o) sred[threadIdx.x] |= sred[threadIdx.x + o];
            __syncthreads();
        }
        if (threadIdx.x == 0) g_odd_or = sred[0];
    }
}

// ---------- degree histogram ----------
__global__ void degree_kernel(const void* __restrict__ ei) {
    int e = blockIdx.x * blockDim.x + threadIdx.x;
    if (e >= EE) return;
    bool is64 = (g_odd_or == 0u);
    unsigned dst = (unsigned)edge_idx(ei, 1, e, is64);
    if (dst < NN) atomicAdd(&g_cnt[dst], 1);
}

// ---------- single-pass scan (decoupled lookback) ----------
__global__ void __launch_bounds__(256) scan_kernel() {
    __shared__ int s[256];
    __shared__ int sprefix;
    const int tid = threadIdx.x, b = blockIdx.x;
    int i = b * 256 + tid;
    int v = (i < NN) ? g_cnt[i] : 0;
    s[tid] = v;
    __syncthreads();
    #pragma unroll
    for (int o = 1; o < 256; o <<= 1) {
        int x = (tid >= o) ? s[tid - o] : 0;
        __syncthreads();
        s[tid] += x;
        __syncthreads();
    }
    int agg = s[255];
    if (tid == 0) {
        if (b == 0) {
            sprefix = 0;
            atomicExch(&g_comb[0], (2ull << 32) | (unsigned)agg);
        } else {
            atomicExch(&g_comb[b], (1ull << 32) | (unsigned)agg);
        }
    }
    if (b > 0 && tid < 32) {
        const int lane = tid;
        int prefix = 0;
        int base = b - 1;
        while (true) {
            int idx = base - lane;
            unsigned long long c;
            unsigned st;
            do {
                c = (idx >= 0) ? atomicAdd(&g_comb[idx], 0ull) : (2ull << 32);
                st = (unsigned)(c >> 32);
            } while (__any_sync(0xffffffffu, st == 0));
            int val = (int)(c & 0xffffffffu);
            unsigned m2 = __ballot_sync(0xffffffffu, st == 2);
            if (m2) {
                int firstp = __ffs(m2) - 1;
                int contrib = (lane <= firstp) ? val : 0;
                prefix += __reduce_add_sync(0xffffffffu, contrib);
                break;
            }
            prefix += __reduce_add_sync(0xffffffffu, val);
            base -= 32;
        }
        if (lane == 0) {
            atomicExch(&g_comb[b], (2ull << 32) | (unsigned)(prefix + agg));
            sprefix = prefix;
        }
    }
    __syncthreads();
    if (i < NN) {
        int excl = sprefix + s[tid] - v;
        g_off[i] = excl;
        g_cur[i] = excl;
        g_dis[i] = (v > 0) ? rsqrtf((float)v) : 0.f;
    }
}

// ---------- bucket fill ----------
__global__ void fill_kernel(const void* __restrict__ ei) {
    int e = blockIdx.x * blockDim.x + threadIdx.x;
    if (e >= EE) return;
    bool is64 = (g_odd_or == 0u);
    int src = edge_idx(ei, 0, e, is64);
    int dst = edge_idx(ei, 1, e, is64);
    if ((unsigned)src >= NN || (unsigned)dst >= NN) return;
    int pos = atomicAdd(&g_cur[dst], 1);
    g_esrc[pos] = src;
}

// ---------- nhs: g_nhs[i] = fp16(nh[i] * dis[row]) (stream B) ----------
__global__ void nhs_kernel(const float* __restrict__ nh) {
    int idx = blockIdx.x * blockDim.x + threadIdx.x;
    if (idx < NN * 32) {
        int row = idx >> 5;
        float d = __ldg(&g_dis[row]);
        float4 v = __ldg(reinterpret_cast<const float4*>(nh) + idx);
        g_nhs[2 * idx]     = __floats2half2_rn(v.x * d, v.y * d);
        g_nhs[2 * idx + 1] = __floats2half2_rn(v.z * d, v.w * d);
    }
}

// ---------- aggregate: warp per node, pairwise fp16 pre-add (R13) ----------
__global__ void aggregate_kernel() {
    int w = (blockIdx.x * blockDim.x + threadIdx.x) >> 5;
    int lane = threadIdx.x & 31;
    if (w >= NN) return;
    int off = g_off[w], len = g_cnt[w];
    float4 acc = make_float4(0.f, 0.f, 0.f, 0.f);
    const float2* NHS = reinterpret_cast<const float2*>(g_nhs);
    for (int b = 0; b < len; b += 32) {
        int n = min(32, len - b);
        int src = (lane < n) ? __ldg(&g_esrc[off + b + lane]) : 0;
        int i = 0;
        #pragma unroll 4
        for (; i + 2 <= n; i += 2) {
            int s0 = __shfl_sync(0xffffffffu, src, i);
            int s1 = __shfl_sync(0xffffffffu, src, i + 1);
            float2 r0 = __ldg(NHS + (size_t)s0 * 32 + lane);
            float2 r1 = __ldg(NHS + (size_t)s1 * 32 + lane);
            __half2 p0 = __hadd2(*reinterpret_cast<__half2*>(&r0.x),
                                 *reinterpret_cast<__half2*>(&r1.x));
            __half2 p1 = __hadd2(*reinterpret_cast<__half2*>(&r0.y),
                                 *reinterpret_cast<__half2*>(&r1.y));
            float2 f0 = __half22float2(p0), f1 = __half22float2(p1);
            acc.x += f0.x; acc.y += f0.y; acc.z += f1.x; acc.w += f1.y;
        }
        if (i < n) {
            int s0 = __shfl_sync(0xffffffffu, src, i);
            float2 r0 = __ldg(NHS + (size_t)s0 * 32 + lane);
            float2 f0 = __half22float2(*reinterpret_cast<__half2*>(&r0.x));
            float2 f1 = __half22float2(*reinterpret_cast<__half2*>(&r0.y));
            acc.x += f0.x; acc.y += f0.y; acc.z += f1.x; acc.w += f1.y;
        }
    }
    float dd = g_dis[w];
    g_xh[(size_t)w * 64 + lane * 2]     = __floats2half2_rn(acc.x * dd, acc.y * dd);
    g_xh[(size_t)w * 64 + lane * 2 + 1] = __floats2half2_rn(acc.z * dd, acc.w * dd);
}

// ---------- fused GEMM1+GEMM2: W in registers, block-cooperative ----------
// mma computes D^T = W^T @ X^T (m=outcols, n=nodes, k=feature). 8 warps,
// each owns 16 output columns; W1^T/W2^T A-fragments live in registers for
// the whole kernel (extracted once via ldmatrix from a staging smem that is
// afterwards reused as SX (x-tile) and SH (h-tile)). 2 barriers per tile.
__global__ void __launch_bounds__(256) gemm12_kernel(
    const float* __restrict__ W1, const float* __restrict__ b1,
    const float* __restrict__ W2, const float* __restrict__ b2,
    float* __restrict__ out) {
    __shared__ __align__(16) __half smem[128 * 136];   // 34,816 B
    const int tid = threadIdx.x, lane = tid & 31, warp = tid >> 5;
    const int gid = lane >> 2, tq = lane & 3;
    const int t8 = lane >> 3, tr = lane & 7;

    // stage W^T (fp16) and extract per-warp A-fragments
    uint32_t wf1[8][4], wf2[8][4];
    const int arow = warp * 16 + (t8 & 1) * 8 + tr;
    #pragma unroll
    for (int which = 0; which < 2; ++which) {
        const float* W = which ? W2 : W1;
        __syncthreads();
        for (int idx = tid; idx < DD * DD; idx += 256) {
            int k = idx >> 7, n = idx & 127;
            smem[n * 136 + k] = __float2half(W[idx]);   // sW[n][k] = W[k][n]
        }
        __syncthreads();
        #pragma unroll
        for (int ks = 0; ks < 8; ++ks) {
            uint32_t a = sptr(&smem[arow * 136 + ks * 16 + (t8 >> 1) * 8]);
            if (which) ldsm4(wf2[ks], a); else ldsm4(wf1[ks], a);
        }
    }
    __syncthreads();
    const float bb10 = __ldg(&b1[warp * 16 + gid]);
    const float bb11 = __ldg(&b1[warp * 16 + gid + 8]);
    const float bb20 = __ldg(&b2[warp * 16 + gid]);
    const float bb21 = __ldg(&b2[warp * 16 + gid + 8]);

    __half* SX = smem;              // [16][136]
    __half* SH = smem + 16 * 136;   // [16][136]

    for (int mt = blockIdx.x; mt < MTILES; mt += gridDim.x) {
        // stage X tile: 16 nodes x 128 feats fp16, 1 uint4 per thread
        {
            int row = tid >> 4, g = tid & 15;
            uint4 v = __ldg(reinterpret_cast<const uint4*>(
                                g_xh + (size_t)(mt * 16 + row) * 64) + g);
            *reinterpret_cast<uint4*>(&SX[row * 136 + g * 8]) = v;
        }
        __syncthreads();

        // GEMM1: h = relu(x@W1+b1) -> SH
        {
            float c0[4] = {0, 0, 0, 0}, c1[4] = {0, 0, 0, 0};
            #pragma unroll
            for (int ks = 0; ks < 8; ++ks) {
                uint32_t b[4];
                ldsm4(b, sptr(&SX[((t8 >> 1) * 8 + tr) * 136 + ks * 16 + (t8 & 1) * 8]));
                mma16816(c0, wf1[ks], b[0], b[1]);   // nodes 0-7
                mma16816(c1, wf1[ks], b[2], b[3]);   // nodes 8-15
            }
            int oc0 = warp * 16 + gid, oc1 = oc0 + 8;
            int n0 = 2 * tq, n1 = n0 + 1;
            SH[n0 * 136 + oc0] = __float2half(fmaxf(c0[0] + bb10, 0.f));
            SH[n1 * 136 + oc0] = __float2half(fmaxf(c0[1] + bb10, 0.f));
            SH[n0 * 136 + oc1] = __float2half(fmaxf(c0[2] + bb11, 0.f));
            SH[n1 * 136 + oc1] = __float2half(fmaxf(c0[3] + bb11, 0.f));
            SH[(n0 + 8) * 136 + oc0] = __float2half(fmaxf(c1[0] + bb10, 0.f));
            SH[(n1 + 8) * 136 + oc0] = __float2half(fmaxf(c1[1] + bb10, 0.f));
            SH[(n0 + 8) * 136 + oc1] = __float2half(fmaxf(c1[2] + bb11, 0.f));
            SH[(n1 + 8) * 136 + oc1] = __float2half(fmaxf(c1[3] + bb11, 0.f));
        }
        __syncthreads();

        // GEMM2: out = h@W2+b2 -> global
        {
            float c0[4] = {0, 0, 0, 0}, c1[4] = {0, 0, 0, 0};
            #pragma unroll
            for (int ks = 0; ks < 8; ++ks) {
                uint32_t b[4];
                ldsm4(b, sptr(&SH[((t8 >> 1) * 8 + tr) * 136 + ks * 16 + (t8 & 1) * 8]));
                mma16816(c0, wf2[ks], b[0], b[1]);
                mma16816(c1, wf2[ks], b[2], b[3]);
            }
            int oc0 = warp * 16 + gid, oc1 = oc0 + 8;
            size_t r = (size_t)(mt * 16 + 2 * tq) * DD;
            out[r + oc0]       = c0[0] + bb20;
            out[r + DD + oc0]  = c0[1] + bb20;
            out[r + oc1]       = c0[2] + bb21;
            out[r + DD + oc1]  = c0[3] + bb21;
            size_t r8 = r + (size_t)8 * DD;
            out[r8 + oc0]      = c1[0] + bb20;
            out[r8 + DD + oc0] = c1[1] + bb20;
            out[r8 + oc1]      = c1[2] + bb21;
            out[r8 + DD + oc1] = c1[3] + bb21;
        }
        // no barrier needed here: next stage writes SX only, and every warp
        // past the post-SH barrier has finished its SX reads.
    }
}

// ---------- eh passthrough (stream C) ----------
__global__ void copy_eh_kernel(const float* __restrict__ eh, float* __restrict__ out) {
    int idx = blockIdx.x * blockDim.x + threadIdx.x;
    const int total4 = EE * 16 / 4;
    if (idx < total4)
        reinterpret_cast<float4*>(out)[idx] =
            __ldg(reinterpret_cast<const float4*>(eh) + idx);
}

extern "C" void kernel_launch(void* const* d_in, const int* in_sizes, int n_in,
                              void* d_out, int out_size) {
    const float* nh = nullptr; const float* eh = nullptr; const void* ei = nullptr;
    const float* Wp[2] = {nullptr, nullptr}; const float* bp[2] = {nullptr, nullptr};
    int nw = 0, nb = 0;
    for (int i = 0; i < n_in; ++i) {
        int s = in_sizes[i];
        if (s == NN * DD)            nh = (const float*)d_in[i];
        else if (s == EE * 16)       eh = (const float*)d_in[i];
        else if (s == 2 * EE)        ei = d_in[i];
        else if (s == DD * DD) { if (nw < 2) Wp[nw++] = (const float*)d_in[i]; }
        else if (s == DD)      { if (nb < 2) bp[nb++] = (const float*)d_in[i]; }
    }
    float* out = (float*)d_out;

    // Lazy one-time setup (first call is uncaptured; reused inside capture).
    static cudaStream_t sB = nullptr, sC = nullptr;
    static cudaEvent_t evFork = nullptr, evScan = nullptr,
                       evNhs = nullptr, evEh = nullptr;
    if (!sB) {
        cudaStreamCreateWithFlags(&sB, cudaStreamNonBlocking);
        cudaStreamCreateWithFlags(&sC, cudaStreamNonBlocking);
        cudaEventCreateWithFlags(&evFork, cudaEventDisableTiming);
        cudaEventCreateWithFlags(&evScan, cudaEventDisableTiming);
        cudaEventCreateWithFlags(&evNhs,  cudaEventDisableTiming);
        cudaEventCreateWithFlags(&evEh,   cudaEventDisableTiming);
    }

    // ---- stream C: eh passthrough (fully independent) ----
    cudaEventRecord(evFork, 0);
    cudaStreamWaitEvent(sC, evFork, 0);
    copy_eh_kernel<<<(EE * 16 / 4 + 255) / 256, 256, 0, sC>>>(
        eh, out + (size_t)NN * DD);
    cudaEventRecord(evEh, sC);

    // ---- stream A: CSR chain ----
    init_kernel<<<NBLK, 256>>>((const unsigned*)ei);
    degree_kernel<<<(EE + 255) / 256, 256>>>(ei);
    scan_kernel<<<NBLK, 256>>>();
    cudaEventRecord(evScan, 0);
    fill_kernel<<<(EE + 255) / 256, 256>>>(ei);

    // ---- stream B: pre-scaled fp16 features (overlaps fill) ----
    cudaStreamWaitEvent(sB, evScan, 0);
    nhs_kernel<<<(NN * 32 + 255) / 256, 256, 0, sB>>>(nh);
    cudaEventRecord(evNhs, sB);

    // ---- aggregate + fused GEMM (serial: overlap disproven twice) ----
    cudaStreamWaitEvent(0, evNhs, 0);
    aggregate_kernel<<<(NN * 32 + 255) / 256, 256>>>();
    gemm12_kernel<<<296, 256>>>(Wp[0], bp[0], Wp[1], bp[1], out);

    // join stream C
    cudaStreamWaitEvent(0, evEh, 0);
}

// round 16
// speedup vs baseline: 1.1580x; 1.0997x over previous
#include <cuda_runtime.h>
#include <cuda_fp16.h>
#include <cstdint>

// GCN layer on GB300, round-16: direct-bucket CSR (no init/degree/scan).
//   A: fill_direct -> nhs -> aggregate(+cnt reset) -> gemm12(+spill reset)
//   C: eh passthrough copy (fully parallel).
// cnt doubles as histogram and cursor; buckets are fixed 64 slots/node
// (Poisson-16 degrees; overflow handled via spill list, P~1e-20).
// State self-resets each call (aggregate zeroes cnt, gemm zeroes spillcnt),
// and __device__ globals are zero-initialized, so replays are clean.

#define NN 100000
#define EE 1600000
#define DD 128
#define MTILES 6250        // 100000/16
#define CAP 64             // bucket slots per node
#define SPILLCAP 1048576
#define WSTRIDE 136
#define SMEM_GEMM (2 * DD * WSTRIDE * (int)sizeof(__half))   // 69,632B

__device__ __align__(128) int     g_cnt[NN];
__device__ __align__(128) int     g_esrc[(size_t)NN * CAP];  // 25.6MB
__device__ __align__(128) int2    g_spill[SPILLCAP];
__device__ __align__(128) __half2 g_nhs[(size_t)NN * 64];    // nh*dis fp16
__device__ __align__(128) __half2 g_xh [(size_t)NN * 64];    // agg fp16
__device__ int g_spillcnt;

// ---------- helpers ----------
__device__ __forceinline__ int edge_idx(const void* ei, int table, int e, bool is64) {
    if (is64) return (int)((const long long*)ei)[(size_t)table * EE + e];
    return ((const int*)ei)[(size_t)table * EE + e];
}
__device__ __forceinline__ uint32_t h2bits(__half2 h) {
    return *reinterpret_cast<uint32_t*>(&h);
}
__device__ __forceinline__ uint32_t packh2(float a, float b) {
    __half2 h = __floats2half2_rn(a, b);
    return *reinterpret_cast<uint32_t*>(&h);
}
__device__ __forceinline__ void mma16816(float c[4], const uint32_t a[4],
                                         uint32_t b0, uint32_t b1) {
    asm volatile(
        "mma.sync.aligned.m16n8k16.row.col.f32.f16.f16.f32 "
        "{%0,%1,%2,%3}, {%4,%5,%6,%7}, {%8,%9}, {%0,%1,%2,%3};"
        : "+f"(c[0]), "+f"(c[1]), "+f"(c[2]), "+f"(c[3])
        : "r"(a[0]), "r"(a[1]), "r"(a[2]), "r"(a[3]), "r"(b0), "r"(b1));
}
// Per-warp index-dtype detect: first 32 odd 32-bit words of edge_index.
// int64 (values < 2^31): all zero. int32: random indices, P(all 0)~1e-160.
// Reads 128B from the buffer head — safe for both dtypes; L1-cached.
__device__ __forceinline__ bool detect_is64(const void* ei, int lane) {
    unsigned hv = ((const unsigned*)ei)[2 * lane + 1];
    return __ballot_sync(0xffffffffu, hv != 0u) == 0u;
}

// ---------- fill_direct: histogram + bucket fill in one pass ----------
__global__ void fill_kernel(const void* __restrict__ ei) {
    const int lane = threadIdx.x & 31;
    const bool is64 = detect_is64(ei, lane);
    int e = blockIdx.x * 256 + threadIdx.x;      // EE == 6250*256 exactly
    int src = edge_idx(ei, 0, e, is64);
    int dst = edge_idx(ei, 1, e, is64);
    if ((unsigned)src >= NN || (unsigned)dst >= NN) return;
    int pos = atomicAdd(&g_cnt[dst], 1);
    if (pos < CAP) {
        g_esrc[(size_t)dst * CAP + pos] = src;
    } else {
        int sp = atomicAdd(&g_spillcnt, 1);
        if (sp < SPILLCAP) g_spill[sp] = make_int2(src, dst);
    }
}

// ---------- nhs: g_nhs[i] = fp16(nh[i] * dis[row]), dis inline ----------
__global__ void nhs_kernel(const float* __restrict__ nh) {
    int idx = blockIdx.x * blockDim.x + threadIdx.x;
    if (idx < NN * 32) {
        int row = idx >> 5;
        int c = __ldg(&g_cnt[row]);
        float d = (c > 0) ? rsqrtf((float)c) : 0.f;
        float4 v = __ldg(reinterpret_cast<const float4*>(nh) + idx);
        g_nhs[2 * idx]     = __floats2half2_rn(v.x * d, v.y * d);
        g_nhs[2 * idx + 1] = __floats2half2_rn(v.z * d, v.w * d);
    }
}

// ---------- aggregate: warp/node, pairwise fp16 pre-add, bucket read ------
// g_xh[d] = fp16( (sum_e g_nhs[src_e]) * dis[d] ); resets cnt for replay.
__global__ void aggregate_kernel() {
    int w = (blockIdx.x * blockDim.x + threadIdx.x) >> 5;
    int lane = threadIdx.x & 31;
    if (w >= NN) return;
    int len = g_cnt[w];
    int blen = min(len, CAP);
    const int* bucket = g_esrc + (size_t)w * CAP;
    float4 acc = make_float4(0.f, 0.f, 0.f, 0.f);
    const float2* NHS = reinterpret_cast<const float2*>(g_nhs);
    for (int b = 0; b < blen; b += 32) {
        int n = min(32, blen - b);
        int src = (lane < n) ? __ldg(&bucket[b + lane]) : 0;
        int i = 0;
        #pragma unroll 4
        for (; i + 2 <= n; i += 2) {
            int s0 = __shfl_sync(0xffffffffu, src, i);
            int s1 = __shfl_sync(0xffffffffu, src, i + 1);
            float2 r0 = __ldg(NHS + (size_t)s0 * 32 + lane);
            float2 r1 = __ldg(NHS + (size_t)s1 * 32 + lane);
            __half2 p0 = __hadd2(*reinterpret_cast<__half2*>(&r0.x),
                                 *reinterpret_cast<__half2*>(&r1.x));
            __half2 p1 = __hadd2(*reinterpret_cast<__half2*>(&r0.y),
                                 *reinterpret_cast<__half2*>(&r1.y));
            float2 f0 = __half22float2(p0), f1 = __half22float2(p1);
            acc.x += f0.x; acc.y += f0.y; acc.z += f1.x; acc.w += f1.y;
        }
        if (i < n) {
            int s0 = __shfl_sync(0xffffffffu, src, i);
            float2 r0 = __ldg(NHS + (size_t)s0 * 32 + lane);
            float2 f0 = __half22float2(*reinterpret_cast<__half2*>(&r0.x));
            float2 f1 = __half22float2(*reinterpret_cast<__half2*>(&r0.y));
            acc.x += f0.x; acc.y += f0.y; acc.z += f1.x; acc.w += f1.y;
        }
    }
    // spill sweep (only for nodes whose bucket overflowed; expected never)
    if (len > CAP) {
        int sc = min(g_spillcnt, SPILLCAP);
        for (int j = 0; j < sc; ++j) {
            int2 eg = g_spill[j];           // broadcast read
            if (eg.y == w) {
                float2 r0 = __ldg(NHS + (size_t)eg.x * 32 + lane);
                float2 f0 = __half22float2(*reinterpret_cast<__half2*>(&r0.x));
                float2 f1 = __half22float2(*reinterpret_cast<__half2*>(&r0.y));
                acc.x += f0.x; acc.y += f0.y; acc.z += f1.x; acc.w += f1.y;
            }
        }
    }
    float dd = (len > 0) ? rsqrtf((float)len) : 0.f;
    g_xh[(size_t)w * 64 + lane * 2]     = __floats2half2_rn(acc.x * dd, acc.y * dd);
    g_xh[(size_t)w * 64 + lane * 2 + 1] = __floats2half2_rn(acc.z * dd, acc.w * dd);
    if (lane == 0) g_cnt[w] = 0;        // reset for next graph replay
}

// ---------- fused GEMM1+GEMM2, register-chained HMMA (R13, best) ----------
__global__ void __launch_bounds__(256) gemm12_kernel(
    const float* __restrict__ W1, const float* __restrict__ b1,
    const float* __restrict__ W2, const float* __restrict__ b2,
    float* __restrict__ out) {
    if (blockIdx.x == 0 && threadIdx.x == 0) g_spillcnt = 0;  // replay reset
    extern __shared__ __half sW[];
    __half* sW1 = sW;
    __half* sW2 = sW + DD * WSTRIDE;
    const int tid = threadIdx.x, lane = tid & 31, warp = tid >> 5;
    const int gid = lane >> 2, tq = lane & 3;

    for (int idx = tid; idx < DD * DD; idx += 256) {
        int k = idx >> 7, n = idx & 127;
        sW1[n * WSTRIDE + k] = __float2half(W1[idx]);
        sW2[n * WSTRIDE + k] = __float2half(W2[idx]);
    }
    __syncthreads();

    for (int mt = blockIdx.x * 8 + warp; mt < MTILES; mt += gridDim.x * 8) {
        const __half2* X0 = g_xh + (size_t)(mt * 16 + gid) * 64;
        const __half2* X1 = X0 + 8 * 64;

        float acc1[16][4];
        #pragma unroll
        for (int t = 0; t < 16; ++t)
            acc1[t][0] = acc1[t][1] = acc1[t][2] = acc1[t][3] = 0.f;
        #pragma unroll
        for (int kc = 0; kc < 8; ++kc) {
            uint32_t a[4];
            a[0] = h2bits(__ldg(X0 + kc * 8 + tq));
            a[1] = h2bits(__ldg(X1 + kc * 8 + tq));
            a[2] = h2bits(__ldg(X0 + kc * 8 + 4 + tq));
            a[3] = h2bits(__ldg(X1 + kc * 8 + 4 + tq));
            #pragma unroll
            for (int t = 0; t < 16; ++t) {
                int n = 8 * t + gid;
                uint32_t b0 = h2bits(*reinterpret_cast<const __half2*>(
                    &sW1[n * WSTRIDE + kc * 16 + 2 * tq]));
                uint32_t b1v = h2bits(*reinterpret_cast<const __half2*>(
                    &sW1[n * WSTRIDE + kc * 16 + 8 + 2 * tq]));
                mma16816(acc1[t], a, b0, b1v);
            }
        }

        float acc2[16][4];
        #pragma unroll
        for (int t = 0; t < 16; ++t)
            acc2[t][0] = acc2[t][1] = acc2[t][2] = acc2[t][3] = 0.f;
        #pragma unroll
        for (int kc = 0; kc < 8; ++kc) {
            int t0 = 2 * kc, t1 = 2 * kc + 1;
            float2 bbA = __ldg(reinterpret_cast<const float2*>(b1 + 8 * t0 + 2 * tq));
            float2 bbB = __ldg(reinterpret_cast<const float2*>(b1 + 8 * t1 + 2 * tq));
            uint32_t ha[4];
            ha[0] = packh2(fmaxf(acc1[t0][0] + bbA.x, 0.f),
                           fmaxf(acc1[t0][1] + bbA.y, 0.f));
            ha[1] = packh2(fmaxf(acc1[t0][2] + bbA.x, 0.f),
                           fmaxf(acc1[t0][3] + bbA.y, 0.f));
            ha[2] = packh2(fmaxf(acc1[t1][0] + bbB.x, 0.f),
                           fmaxf(acc1[t1][1] + bbB.y, 0.f));
            ha[3] = packh2(fmaxf(acc1[t1][2] + bbB.x, 0.f),
                           fmaxf(acc1[t1][3] + bbB.y, 0.f));
            #pragma unroll
            for (int t = 0; t < 16; ++t) {
                int n = 8 * t + gid;
                uint32_t b0 = h2bits(*reinterpret_cast<const __half2*>(
                    &sW2[n * WSTRIDE + kc * 16 + 2 * tq]));
                uint32_t b1v = h2bits(*reinterpret_cast<const __half2*>(
                    &sW2[n * WSTRIDE + kc * 16 + 8 + 2 * tq]));
                mma16816(acc2[t], ha, b0, b1v);
            }
        }

        size_t r0 = (size_t)(mt * 16 + gid) * DD;
        size_t r1 = r0 + (size_t)8 * DD;
        #pragma unroll
        for (int t = 0; t < 16; ++t) {
            int n0 = 8 * t + 2 * tq;
            float2 bb = __ldg(reinterpret_cast<const float2*>(b2 + n0));
            *reinterpret_cast<float2*>(out + r0 + n0) =
                make_float2(acc2[t][0] + bb.x, acc2[t][1] + bb.y);
            *reinterpret_cast<float2*>(out + r1 + n0) =
                make_float2(acc2[t][2] + bb.x, acc2[t][3] + bb.y);
        }
    }
}

// ---------- eh passthrough (stream C) ----------
__global__ void copy_eh_kernel(const float* __restrict__ eh, float* __restrict__ out) {
    int idx = blockIdx.x * blockDim.x + threadIdx.x;
    const int total4 = EE * 16 / 4;
    if (idx < total4)
        reinterpret_cast<float4*>(out)[idx] =
            __ldg(reinterpret_cast<const float4*>(eh) + idx);
}

extern "C" void kernel_launch(void* const* d_in, const int* in_sizes, int n_in,
                              void* d_out, int out_size) {
    const float* nh = nullptr; const float* eh = nullptr; const void* ei = nullptr;
    const float* Wp[2] = {nullptr, nullptr}; const float* bp[2] = {nullptr, nullptr};
    int nw = 0, nb = 0;
    for (int i = 0; i < n_in; ++i) {
        int s = in_sizes[i];
        if (s == NN * DD)            nh = (const float*)d_in[i];
        else if (s == EE * 16)       eh = (const float*)d_in[i];
        else if (s == 2 * EE)        ei = d_in[i];
        else if (s == DD * DD) { if (nw < 2) Wp[nw++] = (const float*)d_in[i]; }
        else if (s == DD)      { if (nb < 2) bp[nb++] = (const float*)d_in[i]; }
    }
    float* out = (float*)d_out;

    // Lazy one-time setup (first call is uncaptured; reused inside capture).
    static cudaStream_t sC = nullptr;
    static cudaEvent_t evFork = nullptr, evEh = nullptr;
    static bool attrSet = false;
    if (!sC) {
        cudaStreamCreateWithFlags(&sC, cudaStreamNonBlocking);
        cudaEventCreateWithFlags(&evFork, cudaEventDisableTiming);
        cudaEventCreateWithFlags(&evEh,   cudaEventDisableTiming);
    }
    if (!attrSet) {
        cudaFuncSetAttribute(gemm12_kernel,
                             cudaFuncAttributeMaxDynamicSharedMemorySize, SMEM_GEMM);
        attrSet = true;
    }

    // ---- stream C: eh passthrough (fully independent) ----
    cudaEventRecord(evFork, 0);
    cudaStreamWaitEvent(sC, evFork, 0);
    copy_eh_kernel<<<(EE * 16 / 4 + 255) / 256, 256, 0, sC>>>(
        eh, out + (size_t)NN * DD);
    cudaEventRecord(evEh, sC);

    // ---- stream A: 4-kernel chain ----
    fill_kernel<<<EE / 256, 256>>>(ei);
    nhs_kernel<<<(NN * 32 + 255) / 256, 256>>>(nh);
    aggregate_kernel<<<(NN * 32 + 255) / 256, 256>>>();
    gemm12_kernel<<<296, 256, SMEM_GEMM>>>(Wp[0], bp[0], Wp[1], bp[1], out);

    // join stream C
    cudaStreamWaitEvent(0, evEh, 0);
}